// round 1
// baseline (speedup 1.0000x reference)
#include <cuda_runtime.h>
#include <math.h>

#define NB    16
#define CIN   256
#define HW    1024
#define INNER 512
#define CTXN  77
#define CTXD  768
#define DH    64

// ------------------------------ scratch (device globals, no allocs) ---------
__device__ __align__(16) float g_xn[NB * HW * CIN];      // GN1(x) in [b,n,c]
__device__ __align__(16) float g_h0[NB * HW * INNER];    // conv_in out
__device__ __align__(16) float g_hn[NB * HW * INNER];    // GN2(h0); reused as h2
__device__ __align__(16) float g_q [NB * HW * INNER];    // SA q; reused as CA q
__device__ __align__(16) float g_k [NB * HW * INNER];
__device__ __align__(16) float g_v [NB * HW * INNER];
__device__ __align__(16) float g_sim[(long)NB * HW * HW];
__device__ __align__(16) float g_o [NB * HW * INNER];    // SA attn out; reused CA out
__device__ __align__(16) float g_h1[NB * HW * INNER];    // after SA block
__device__ __align__(16) float g_kc[NB * CTXN * INNER];
__device__ __align__(16) float g_vc[NB * CTXN * INNER];
__device__ float g_stats[NB * 32 * 2];                   // GN1 mean/rstd

// ------------------------------ reductions ----------------------------------
__device__ __forceinline__ float warpSum(float v) {
#pragma unroll
    for (int o = 16; o; o >>= 1) v += __shfl_xor_sync(0xffffffffu, v, o);
    return v;
}
__device__ __forceinline__ float warpMax(float v) {
#pragma unroll
    for (int o = 16; o; o >>= 1) v = fmaxf(v, __shfl_xor_sync(0xffffffffu, v, o));
    return v;
}
__device__ float blockSum(float v) {   // 256 threads
    __shared__ float sm[8];
    int t = threadIdx.x;
    v = warpSum(v);
    if ((t & 31) == 0) sm[t >> 5] = v;
    __syncthreads();
    if (t < 32) {
        float w = (t < 8) ? sm[t] : 0.f;
        w = warpSum(w);
        if (t == 0) sm[0] = w;
    }
    __syncthreads();
    float r = sm[0];
    __syncthreads();
    return r;
}
__device__ float blockMax(float v) {
    __shared__ float sm[8];
    int t = threadIdx.x;
    v = warpMax(v);
    if ((t & 31) == 0) sm[t >> 5] = v;
    __syncthreads();
    if (t < 32) {
        float w = (t < 8) ? sm[t] : -3.0e38f;
        w = warpMax(w);
        if (t == 0) sm[0] = w;
    }
    __syncthreads();
    float r = sm[0];
    __syncthreads();
    return r;
}

// ------------------------------ GroupNorm 1 (on x, NCHW) --------------------
__global__ void gn1_stats_k(const float* __restrict__ x) {
    int bg = blockIdx.x;                       // b*32+g ; 8 ch * 1024 sp = 8192 contiguous
    const float* p = x + (long)bg * 8192;
    float s = 0.f, ss = 0.f;
    for (int i = threadIdx.x; i < 8192; i += 256) {
        float v = p[i]; s += v; ss += v * v;
    }
    s = blockSum(s); ss = blockSum(ss);
    if (threadIdx.x == 0) {
        float mean = s * (1.f / 8192.f);
        float var  = ss * (1.f / 8192.f) - mean * mean;
        g_stats[bg * 2]     = mean;
        g_stats[bg * 2 + 1] = rsqrtf(var + 1e-5f);
    }
}
// normalize + NCHW -> [b,n,c] transpose (coalesced writes; reads hit L2)
__global__ void gn1_apply_k(const float* __restrict__ x,
                            const float* __restrict__ gam,
                            const float* __restrict__ bet) {
    int idx = blockIdx.x * 256 + threadIdx.x;   // [b,n,c] linear, c fastest
    int c = idx & 255;
    int n = (idx >> 8) & 1023;
    int b = idx >> 18;
    float v = x[((long)(b * 256 + c)) * 1024 + n];
    int sg = (b << 5) | (c >> 3);
    float mean = g_stats[sg * 2], rstd = g_stats[sg * 2 + 1];
    g_xn[idx] = (v - mean) * rstd * gam[c] + bet[c];
}

// ------------------------------ GroupNorm 2 (on h0, [b,n,c]) ----------------
__global__ void gn2_k(const float* __restrict__ gg, const float* __restrict__ gb) {
    int b = blockIdx.x >> 5, g = blockIdx.x & 31;     // 16 channels per group
    const float* p = g_h0 + (long)b * HW * INNER + g * 16;
    float s = 0.f, ss = 0.f;
    for (int i = threadIdx.x; i < HW * 16; i += 256) {
        int n = i >> 4, j = i & 15;
        float v = p[n * INNER + j]; s += v; ss += v * v;
    }
    s = blockSum(s); ss = blockSum(ss);
    float mean = s * (1.f / 16384.f);
    float rstd = rsqrtf(ss * (1.f / 16384.f) - mean * mean + 1e-5f);
    float* q = g_hn + (long)b * HW * INNER + g * 16;
    for (int i = threadIdx.x; i < HW * 16; i += 256) {
        int n = i >> 4, j = i & 15;
        int c = g * 16 + j;
        q[n * INNER + j] = (p[n * INNER + j] - mean) * rstd * gg[c] + gb[c];
    }
}

// ------------------------------ softmax over 1024 ---------------------------
__global__ void softmax_k() {
    float4* row = (float4*)(g_sim + (long)blockIdx.x * HW);
    float4 v = row[threadIdx.x];
    float m = blockMax(fmaxf(fmaxf(v.x, v.y), fmaxf(v.z, v.w)));
    v.x = __expf(v.x - m); v.y = __expf(v.y - m);
    v.z = __expf(v.z - m); v.w = __expf(v.w - m);
    float inv = 1.f / blockSum(v.x + v.y + v.z + v.w);
    v.x *= inv; v.y *= inv; v.z *= inv; v.w *= inv;
    row[threadIdx.x] = v;
}

// ------------------------------ fused cross-attention -----------------------
// One block per (b, head). K/V for the head live in smem (77x64 fp32 x2).
__global__ void __launch_bounds__(256) ca_attn_k() {
    __shared__ float Ks[CTXN][DH];
    __shared__ float Vs[CTXN][DH];
    int b = blockIdx.x >> 3, h = blockIdx.x & 7;
    const float* kp = g_kc + (long)b * CTXN * INNER + h * DH;
    const float* vp = g_vc + (long)b * CTXN * INNER + h * DH;
    for (int i = threadIdx.x; i < CTXN * DH; i += 256) {
        int j = i >> 6, d = i & 63;
        Ks[j][d] = kp[j * INNER + d];
        Vs[j][d] = vp[j * INNER + d];
    }
    __syncthreads();
    const float scale = 0.125f;   // 64^-0.5
    for (int i = threadIdx.x; i < HW; i += 256) {
        const float* qp = g_q + ((long)(b * HW + i)) * INNER + h * DH;
        float qv[DH];
#pragma unroll
        for (int d = 0; d < DH; d += 4) {
            float4 t = *(const float4*)(qp + d);
            qv[d] = t.x; qv[d + 1] = t.y; qv[d + 2] = t.z; qv[d + 3] = t.w;
        }
        float mx = -3.0e38f, l = 0.f, acc[DH];
#pragma unroll
        for (int d = 0; d < DH; d++) acc[d] = 0.f;
        for (int j = 0; j < CTXN; j++) {
            float s = 0.f;
#pragma unroll
            for (int d = 0; d < DH; d++) s += qv[d] * Ks[j][d];
            s *= scale;
            float nm   = fmaxf(mx, s);
            float corr = __expf(mx - nm);
            float pr   = __expf(s - nm);
            l = l * corr + pr;
#pragma unroll
            for (int d = 0; d < DH; d++) acc[d] = acc[d] * corr + pr * Vs[j][d];
            mx = nm;
        }
        float inv = 1.f / l;
        float* op = g_o + ((long)(b * HW + i)) * INNER + h * DH;
#pragma unroll
        for (int d = 0; d < DH; d += 4) {
            float4 t = make_float4(acc[d] * inv, acc[d + 1] * inv,
                                   acc[d + 2] * inv, acc[d + 3] * inv);
            *(float4*)(op + d) = t;
        }
    }
}

// ------------------------------ generic batched SGEMM -----------------------
// C[bz][m,n] = alpha * sum_k A[m,k] * B(k,n)  (+ bias[n]) (+ rcoef * R[idx])
// BT:   B is [N,K] row-major (weights / k-matrix)   else B is [K,N]
// TOUT: store at bz*M*N + n*M + m (NCHW epilogue), residual read same idx
template <bool BT, bool TOUT>
__global__ void __launch_bounds__(256) gemm_k(
    const float* __restrict__ A, long sA,
    const float* __restrict__ Bm, long sB,
    float* __restrict__ C,
    const float* __restrict__ bias,
    const float* __restrict__ R, float rcoef,
    float alpha, int M, int N, int K) {
    __shared__ float As[8][128];
    __shared__ float Bs[8][128];
    const int bz = blockIdx.z;
    const float* Ab = A + (long)bz * sA;
    const float* Bb = Bm + (long)bz * sB;
    const int bm = blockIdx.y * 128;
    const int bn = blockIdx.x * 128;
    const int tid = threadIdx.x;
    const int tx = tid & 15, ty = tid >> 4;

    float acc[8][8];
#pragma unroll
    for (int i = 0; i < 8; i++)
#pragma unroll
        for (int j = 0; j < 8; j++) acc[i][j] = 0.f;

    const int lr = tid >> 1;            // 0..127
    const int lc = (tid & 1) * 4;       // 0 or 4
    const int nkr = tid >> 5;           // NN: k-row 0..7
    const int nnc = (tid & 31) * 4;     // NN: n-col

    for (int k0 = 0; k0 < K; k0 += 8) {
        float4 av = make_float4(0.f, 0.f, 0.f, 0.f);
        if (bm + lr < M) av = *(const float4*)(Ab + (long)(bm + lr) * K + k0 + lc);
        As[lc + 0][lr] = av.x; As[lc + 1][lr] = av.y;
        As[lc + 2][lr] = av.z; As[lc + 3][lr] = av.w;
        if (BT) {
            float4 bv = *(const float4*)(Bb + (long)(bn + lr) * K + k0 + lc);
            Bs[lc + 0][lr] = bv.x; Bs[lc + 1][lr] = bv.y;
            Bs[lc + 2][lr] = bv.z; Bs[lc + 3][lr] = bv.w;
        } else {
            float4 bv = *(const float4*)(Bb + (long)(k0 + nkr) * N + bn + nnc);
            *(float4*)&Bs[nkr][nnc] = bv;
        }
        __syncthreads();
#pragma unroll
        for (int kk = 0; kk < 8; kk++) {
            float4 a0 = *(const float4*)&As[kk][ty * 8];
            float4 a1 = *(const float4*)&As[kk][ty * 8 + 4];
            float4 b0 = *(const float4*)&Bs[kk][tx * 8];
            float4 b1 = *(const float4*)&Bs[kk][tx * 8 + 4];
            float ar[8] = {a0.x, a0.y, a0.z, a0.w, a1.x, a1.y, a1.z, a1.w};
            float br[8] = {b0.x, b0.y, b0.z, b0.w, b1.x, b1.y, b1.z, b1.w};
#pragma unroll
            for (int i = 0; i < 8; i++)
#pragma unroll
                for (int j = 0; j < 8; j++) acc[i][j] += ar[i] * br[j];
        }
        __syncthreads();
    }
#pragma unroll
    for (int i = 0; i < 8; i++) {
        int m = bm + ty * 8 + i;
        if (m < M) {
#pragma unroll
            for (int j = 0; j < 8; j++) {
                int n = bn + tx * 8 + j;
                float v = acc[i][j] * alpha;
                if (bias) v += bias[n];
                long idx = TOUT ? ((long)bz * M * N + (long)n * M + m)
                                : ((long)bz * M * N + (long)m * N + n);
                if (R) v += rcoef * R[idx];
                C[idx] = v;
            }
        }
    }
}

static void launch_gemm(bool bt, bool tout,
                        const float* A, long sA, const float* Bm, long sB,
                        float* C, const float* bias, const float* R, float rcoef,
                        float alpha, int M, int N, int K) {
    dim3 grid(N / 128, (M + 127) / 128, NB);
    if (bt && tout)
        gemm_k<true, true><<<grid, 256>>>(A, sA, Bm, sB, C, bias, R, rcoef, alpha, M, N, K);
    else if (bt)
        gemm_k<true, false><<<grid, 256>>>(A, sA, Bm, sB, C, bias, R, rcoef, alpha, M, N, K);
    else
        gemm_k<false, false><<<grid, 256>>>(A, sA, Bm, sB, C, bias, R, rcoef, alpha, M, N, K);
}

// ------------------------------ driver --------------------------------------
extern "C" void kernel_launch(void* const* d_in, const int* in_sizes, int n_in,
                              void* d_out, int out_size) {
    const float* x      = (const float*)d_in[0];
    const float* ctx    = (const float*)d_in[1];
    const float* gn1_g  = (const float*)d_in[2];
    const float* gn1_b  = (const float*)d_in[3];
    const float* w_in   = (const float*)d_in[4];
    const float* b_in   = (const float*)d_in[5];
    const float* sa_wk  = (const float*)d_in[6];
    const float* sa_wq  = (const float*)d_in[7];
    const float* sa_wv  = (const float*)d_in[8];
    const float* sa_wp  = (const float*)d_in[9];
    const float* sa_gng = (const float*)d_in[10];
    const float* sa_gnb = (const float*)d_in[11];
    const float* ca_wq  = (const float*)d_in[12];
    const float* ca_wk  = (const float*)d_in[13];
    const float* ca_wv  = (const float*)d_in[14];
    const float* ca_wo  = (const float*)d_in[15];
    const float* ca_bo  = (const float*)d_in[16];
    const float* w_out  = (const float*)d_in[17];
    const float* b_out  = (const float*)d_in[18];
    float* out = (float*)d_out;

    float *xn, *h0, *hn, *q, *k, *v, *sim, *o, *h1, *kc, *vc;
    cudaGetSymbolAddress((void**)&xn,  g_xn);
    cudaGetSymbolAddress((void**)&h0,  g_h0);
    cudaGetSymbolAddress((void**)&hn,  g_hn);
    cudaGetSymbolAddress((void**)&q,   g_q);
    cudaGetSymbolAddress((void**)&k,   g_k);
    cudaGetSymbolAddress((void**)&v,   g_v);
    cudaGetSymbolAddress((void**)&sim, g_sim);
    cudaGetSymbolAddress((void**)&o,   g_o);
    cudaGetSymbolAddress((void**)&h1,  g_h1);
    cudaGetSymbolAddress((void**)&kc,  g_kc);
    cudaGetSymbolAddress((void**)&vc,  g_vc);

    const float inv_sqrt_c = 0.044194173824159216f;   // 512^-0.5

    // 1. GN1(x) -> g_xn [b,n,c]
    gn1_stats_k<<<NB * 32, 256>>>(x);
    gn1_apply_k<<<NB * HW * CIN / 256, 256>>>(x, gn1_g, gn1_b);
    // 2. conv_in: h0 = xn @ w_in^T + b_in
    launch_gemm(true, false, xn, (long)HW * CIN, w_in, 0, h0, b_in,
                nullptr, 0.f, 1.f, HW, INNER, CIN);
    // 3. GN2(h0) -> hn
    gn2_k<<<NB * 32, 256>>>(sa_gng, sa_gnb);
    // 4. q/k/v = hn @ W^T
    launch_gemm(true, false, hn, (long)HW * INNER, sa_wq, 0, q, nullptr, nullptr, 0.f, 1.f, HW, INNER, INNER);
    launch_gemm(true, false, hn, (long)HW * INNER, sa_wk, 0, k, nullptr, nullptr, 0.f, 1.f, HW, INNER, INNER);
    launch_gemm(true, false, hn, (long)HW * INNER, sa_wv, 0, v, nullptr, nullptr, 0.f, 1.f, HW, INNER, INNER);
    // 5. sim = q @ k^T * c^-0.5
    launch_gemm(true, false, q, (long)HW * INNER, k, (long)HW * INNER, sim,
                nullptr, nullptr, 0.f, inv_sqrt_c, HW, HW, INNER);
    // 6. row softmax
    softmax_k<<<NB * HW, 256>>>();
    // 7. o = attn @ v
    launch_gemm(false, false, sim, (long)HW * HW, v, (long)HW * INNER, o,
                nullptr, nullptr, 0.f, 1.f, HW, INNER, HW);
    // 8. h1 = o @ wp^T + 2*h0   (SelfAttention residual + outer residual)
    launch_gemm(true, false, o, (long)HW * INNER, sa_wp, 0, h1, nullptr,
                h0, 2.f, 1.f, HW, INNER, INNER);
    // 9. CA projections
    launch_gemm(true, false, h1, (long)HW * INNER, ca_wq, 0, q, nullptr, nullptr, 0.f, 1.f, HW, INNER, INNER);
    launch_gemm(true, false, ctx, (long)CTXN * CTXD, ca_wk, 0, kc, nullptr, nullptr, 0.f, 1.f, CTXN, INNER, CTXD);
    launch_gemm(true, false, ctx, (long)CTXN * CTXD, ca_wv, 0, vc, nullptr, nullptr, 0.f, 1.f, CTXN, INNER, CTXD);
    // 10. fused 8-head cross-attention -> o
    ca_attn_k<<<NB * 8, 256>>>();
    // 11. h2 = o @ ca_wo^T + ca_bo + h1   (stored in g_hn)
    launch_gemm(true, false, o, (long)HW * INNER, ca_wo, 0, hn, ca_bo,
                h1, 1.f, 1.f, HW, INNER, INNER);
    // 12. out = h2 @ w_out^T + b_out + x   (transposed store -> NCHW)
    launch_gemm(true, true, hn, (long)HW * INNER, w_out, 0, out, b_out,
                x, 1.f, 1.f, HW, CIN, INNER);
}

// round 3
// speedup vs baseline: 3.3570x; 3.3570x over previous
#include <cuda_runtime.h>
#include <cuda_bf16.h>
#include <math.h>
#include <stdint.h>

#define NB    16
#define CIN   256
#define HW    1024
#define INNER 512
#define CTXN  77
#define CTXD  768
#define DH    64

// ===================== PTX helpers (sm_80-safe only) =========================
__device__ __forceinline__ uint32_t smem_to_u32(const void* p) {
    uint32_t a;
    asm("{ .reg .u64 t; cvta.to.shared.u64 t, %1; cvt.u32.u64 %0, t; }" : "=r"(a) : "l"(p));
    return a;
}
__device__ __forceinline__ void cp16(uint32_t dst, const void* src, bool valid) {
    int sz = valid ? 16 : 0;
    asm volatile("cp.async.cg.shared.global [%0], [%1], 16, %2;"
                 :: "r"(dst), "l"(src), "r"(sz) : "memory");
}
#define CP_COMMIT() asm volatile("cp.async.commit_group;" ::: "memory")
#define CP_WAIT0()  asm volatile("cp.async.wait_group 0;" ::: "memory")

__device__ __forceinline__ void ldsm_x4(uint32_t* r, uint32_t addr) {
    asm volatile("ldmatrix.sync.aligned.m8n8.x4.shared.b16 {%0,%1,%2,%3}, [%4];"
        : "=r"(r[0]), "=r"(r[1]), "=r"(r[2]), "=r"(r[3]) : "r"(addr));
}
__device__ __forceinline__ void ldsm_x2(uint32_t* r, uint32_t addr) {
    asm volatile("ldmatrix.sync.aligned.m8n8.x2.shared.b16 {%0,%1}, [%2];"
        : "=r"(r[0]), "=r"(r[1]) : "r"(addr));
}
__device__ __forceinline__ void mma_bf16(float* d, const uint32_t* a, const uint32_t* b) {
    asm volatile(
        "mma.sync.aligned.m16n8k16.row.col.f32.bf16.bf16.f32 "
        "{%0,%1,%2,%3}, {%4,%5,%6,%7}, {%8,%9}, {%0,%1,%2,%3};"
        : "+f"(d[0]), "+f"(d[1]), "+f"(d[2]), "+f"(d[3])
        : "r"(a[0]), "r"(a[1]), "r"(a[2]), "r"(a[3]), "r"(b[0]), "r"(b[1]));
}
__device__ __forceinline__ void mma_tf32(float* d, const uint32_t* a, const uint32_t* b) {
    asm volatile(
        "mma.sync.aligned.m16n8k8.row.col.f32.tf32.tf32.f32 "
        "{%0,%1,%2,%3}, {%4,%5,%6,%7}, {%8,%9}, {%0,%1,%2,%3};"
        : "+f"(d[0]), "+f"(d[1]), "+f"(d[2]), "+f"(d[3])
        : "r"(a[0]), "r"(a[1]), "r"(a[2]), "r"(a[3]), "r"(b[0]), "r"(b[1]));
}
__device__ __forceinline__ uint32_t f2tf32(float v) {
    uint32_t r;
    asm("cvt.rna.tf32.f32 %0, %1;" : "=r"(r) : "f"(v));
    return r;
}

// ===================== scratch (device globals) ==============================
#define WB_TOTAL 3567616L
__device__ __align__(16) __nv_bfloat16 g_wb[WB_TOTAL];
__device__ __align__(16) float g_xnf[NB * HW * CIN];
__device__ __align__(16) float g_h0 [NB * HW * INNER];
__device__ __align__(16) float g_h1 [NB * HW * INNER];
__device__ __align__(16) float g_of [NB * HW * INNER];
__device__ __align__(16) float g_kc [NB * CTXN * INNER];
__device__ __align__(16) float g_vc [NB * CTXN * INNER];
__device__ float g_stats[NB * 32 * 2];
__device__ __align__(16) __nv_bfloat16 g_hnb [NB * HW * INNER];
__device__ __align__(16) __nv_bfloat16 g_qb  [NB * HW * INNER];
__device__ __align__(16) __nv_bfloat16 g_kb  [NB * HW * INNER];
__device__ __align__(16) __nv_bfloat16 g_vtb [NB * HW * INNER];
__device__ __align__(16) __nv_bfloat16 g_h1b [NB * HW * INNER];
__device__ __align__(16) __nv_bfloat16 g_attn[(long)NB * HW * HW];

// ===================== reductions ============================================
__device__ __forceinline__ float warpSum(float v) {
#pragma unroll
    for (int o = 16; o; o >>= 1) v += __shfl_xor_sync(0xffffffffu, v, o);
    return v;
}
__device__ float blockSum(float v) {
    __shared__ float sm[8];
    int t = threadIdx.x;
    v = warpSum(v);
    if ((t & 31) == 0) sm[t >> 5] = v;
    __syncthreads();
    if (t < 32) {
        float w = (t < 8) ? sm[t] : 0.f;
        w = warpSum(w);
        if (t == 0) sm[0] = w;
    }
    __syncthreads();
    float r = sm[0];
    __syncthreads();
    return r;
}
__device__ __forceinline__ float warpMax(float v) {
#pragma unroll
    for (int o = 16; o; o >>= 1) v = fmaxf(v, __shfl_xor_sync(0xffffffffu, v, o));
    return v;
}
__device__ float blockMax(float v) {
    __shared__ float sm[8];
    int t = threadIdx.x;
    v = warpMax(v);
    if ((t & 31) == 0) sm[t >> 5] = v;
    __syncthreads();
    if (t < 32) {
        float w = (t < 8) ? sm[t] : -3.0e38f;
        w = warpMax(w);
        if (t == 0) sm[0] = w;
    }
    __syncthreads();
    float r = sm[0];
    __syncthreads();
    return r;
}

// ===================== conversions ===========================================
struct CvtSrc { const float* p[11]; };
__global__ void cvt_k(CvtSrc a) {
    long i = (long)blockIdx.x * 256 + threadIdx.x;
    if (i >= WB_TOTAL) return;
    const long ends[11] = {131072, 393216, 655360, 917504, 1179648, 1441792,
                           1835008, 2228224, 2490368, 2621440, 3567616};
    int s = 0; long off = 0;
#pragma unroll
    for (int k = 0; k < 11; k++) {
        if (i >= ends[k]) { s = k + 1; off = ends[k]; }
    }
    g_wb[i] = __float2bfloat16(a.p[s][i - off]);
}

// ===================== GroupNorm 1 ===========================================
__global__ void gn1_stats_k(const float* __restrict__ x) {
    int bg = blockIdx.x;
    const float* p = x + (long)bg * 8192;
    float s = 0.f, ss = 0.f;
    for (int i = threadIdx.x; i < 8192; i += 256) {
        float v = p[i]; s += v; ss += v * v;
    }
    s = blockSum(s); ss = blockSum(ss);
    if (threadIdx.x == 0) {
        float mean = s * (1.f / 8192.f);
        float var  = ss * (1.f / 8192.f) - mean * mean;
        g_stats[bg * 2]     = mean;
        g_stats[bg * 2 + 1] = rsqrtf(var + 1e-5f);
    }
}
__global__ void gn1_apply_k(const float* __restrict__ x,
                            const float* __restrict__ gam,
                            const float* __restrict__ bet) {
    int idx = blockIdx.x * 256 + threadIdx.x;
    int c = idx & 255;
    int n = (idx >> 8) & 1023;
    int b = idx >> 18;
    float v = x[((long)(b * 256 + c)) * 1024 + n];
    int sg = (b << 5) | (c >> 3);
    float mean = g_stats[sg * 2], rstd = g_stats[sg * 2 + 1];
    g_xnf[idx] = (v - mean) * rstd * gam[c] + bet[c];
}

// ===================== GroupNorm 2 (h0 fp32 -> hnb bf16) =====================
__global__ void gn2_k(const float* __restrict__ gg, const float* __restrict__ gb) {
    int b = blockIdx.x >> 5, g = blockIdx.x & 31;
    const float* p = g_h0 + (long)b * HW * INNER + g * 16;
    float s = 0.f, ss = 0.f;
    for (int i = threadIdx.x; i < HW * 16; i += 256) {
        int n = i >> 4, j = i & 15;
        float v = p[n * INNER + j]; s += v; ss += v * v;
    }
    s = blockSum(s); ss = blockSum(ss);
    float mean = s * (1.f / 16384.f);
    float rstd = rsqrtf(ss * (1.f / 16384.f) - mean * mean + 1e-5f);
    __nv_bfloat16* q = g_hnb + (long)b * HW * INNER + g * 16;
    for (int i = threadIdx.x; i < HW * 16; i += 256) {
        int n = i >> 4, j = i & 15;
        int c = g * 16 + j;
        q[n * INNER + j] = __float2bfloat16(
            (p[n * INNER + j] - mean) * rstd * gg[c] + gb[c]);
    }
}

// ===================== softmax over 1024 (bf16 in/out) =======================
__global__ void softmax_k() {
    __nv_bfloat162* row = (__nv_bfloat162*)(g_attn + (long)blockIdx.x * HW);
    int t = threadIdx.x;
    __nv_bfloat162 a = row[t * 2], b = row[t * 2 + 1];
    float2 fa = __bfloat1622float2(a), fb = __bfloat1622float2(b);
    float m = blockMax(fmaxf(fmaxf(fa.x, fa.y), fmaxf(fb.x, fb.y)));
    fa.x = __expf(fa.x - m); fa.y = __expf(fa.y - m);
    fb.x = __expf(fb.x - m); fb.y = __expf(fb.y - m);
    float inv = 1.f / blockSum(fa.x + fa.y + fb.x + fb.y);
    fa.x *= inv; fa.y *= inv; fb.x *= inv; fb.y *= inv;
    row[t * 2]     = __floats2bfloat162_rn(fa.x, fa.y);
    row[t * 2 + 1] = __floats2bfloat162_rn(fb.x, fb.y);
}

// ===================== fused cross-attention (fp32 out) ======================
__global__ void __launch_bounds__(256) ca_attn_k() {
    __shared__ float Ks[CTXN][DH];
    __shared__ float Vs[CTXN][DH];
    int b = blockIdx.x >> 3, h = blockIdx.x & 7;
    const float* kp = g_kc + (long)b * CTXN * INNER + h * DH;
    const float* vp = g_vc + (long)b * CTXN * INNER + h * DH;
    for (int i = threadIdx.x; i < CTXN * DH; i += 256) {
        int j = i >> 6, d = i & 63;
        Ks[j][d] = kp[j * INNER + d];
        Vs[j][d] = vp[j * INNER + d];
    }
    __syncthreads();
    const float scale = 0.125f;
    int i = blockIdx.y * 256 + threadIdx.x;
    const __nv_bfloat16* qp = g_qb + ((long)(b * HW + i)) * INNER + h * DH;
    float qv[DH];
#pragma unroll
    for (int d = 0; d < DH; d += 8) {
        uint4 u = *(const uint4*)(qp + d);
        const __nv_bfloat162* h2 = (const __nv_bfloat162*)&u;
#pragma unroll
        for (int e = 0; e < 4; e++) {
            float2 f = __bfloat1622float2(h2[e]);
            qv[d + 2 * e] = f.x; qv[d + 2 * e + 1] = f.y;
        }
    }
    float l = 0.f, acc[DH];
#pragma unroll
    for (int d = 0; d < DH; d++) acc[d] = 0.f;
    for (int j = 0; j < CTXN; j++) {
        float s = 0.f;
#pragma unroll
        for (int d = 0; d < DH; d++) s += qv[d] * Ks[j][d];
        float e = __expf(s * scale);
        l += e;
#pragma unroll
        for (int d = 0; d < DH; d++) acc[d] += e * Vs[j][d];
    }
    float inv = 1.f / l;
    float* op = g_of + ((long)(b * HW + i)) * INNER + h * DH;
#pragma unroll
    for (int d = 0; d < DH; d += 4)
        *(float4*)(op + d) = make_float4(acc[d] * inv, acc[d + 1] * inv,
                                         acc[d + 2] * inv, acc[d + 3] * inv);
}

// ===================== mma.sync GEMM =========================================
// C[bz] = alpha * A[bz] @ B[bz]^T (+ bias[n]) (+ rcoef * R)
// DT=0: bf16 operands, m16n8k16. DT=1: fp32 operands via tf32, m16n8k8.
// A: [M,K] row-major; B: [N,K] row-major (== col-major K x N for mma .col).
// 128x128 CTA tile, 8 warps (2x4), 64x32 warp tiles, cp.async double buffer.
// Smem rows padded to 80B (conflict-free ldmatrix + tf32 lds).
// TOUT: store (and read R) at [bz*M*N + n*M + m].
template <int DT, bool TOUT>
__global__ void __launch_bounds__(256) gemm_mma(
    const void* __restrict__ A_, long sA,
    const void* __restrict__ B_, long sB,
    float* __restrict__ Cf, __nv_bfloat16* __restrict__ Cb,
    const float* __restrict__ bias, const float* __restrict__ R,
    float rcoef, float alpha, int M, int N, int K) {
    constexpr int ESZ = DT ? 4 : 2;
    constexpr int BK  = DT ? 16 : 32;       // elements per chunk (64B of data/row)
    __shared__ __align__(128) char sm[40960];   // A: [0,20480) B: [20480,40960)
    const uint32_t sb = smem_to_u32(sm);
    const int tid  = threadIdx.x;
    const int wid  = tid >> 5;
    const int lane = tid & 31;
    const int bz = blockIdx.z;
    const int bm = blockIdx.y * 128;
    const int bn = blockIdx.x * 128;
    const int wm = (wid >> 2) * 64;
    const int wn = (wid & 3) * 32;
    const char* Ab = (const char*)A_ + (long)bz * sA * ESZ;
    const char* Bb = (const char*)B_ + (long)bz * sB * ESZ;

    float acc[4][4][4];
#pragma unroll
    for (int i = 0; i < 4; i++)
#pragma unroll
        for (int j = 0; j < 4; j++)
#pragma unroll
            for (int e = 0; e < 4; e++) acc[i][j][e] = 0.f;

    const int lrow = tid >> 1;
    const int lu0  = tid & 1;
    const bool aValid = (bm + lrow) < M;
    const long aRow = aValid ? (long)(bm + lrow) * K : 0;
    const long bRow = (long)(bn + lrow) * K;

    const int nIter = K / BK;
#define LOAD_CHUNK(i, s) do {                                                   \
    uint32_t dA = sb + (s) * 10240 + lrow * 80;                                 \
    uint32_t dB = dA + 20480;                                                   \
    long kof = (long)(i) * BK;                                                  \
    _Pragma("unroll")                                                           \
    for (int j = 0; j < 2; j++) {                                               \
        int u = lu0 + 2 * j;                                                    \
        cp16(dA + u * 16, Ab + (aRow + kof) * ESZ + u * 16, aValid);            \
        cp16(dB + u * 16, Bb + (bRow + kof) * ESZ + u * 16, true);              \
    }                                                                           \
} while (0)

    LOAD_CHUNK(0, 0);
    CP_COMMIT();

    const int tr  = lane >> 2;
    const int tcq = lane & 3;

    for (int it = 0; it < nIter; it++) {
        const int s = it & 1;
        CP_WAIT0();
        __syncthreads();
        if (it + 1 < nIter) {
            LOAD_CHUNK(it + 1, s ^ 1);
            CP_COMMIT();
        }
        if (DT == 0) {
            const uint32_t aT = sb + s * 10240;
            const uint32_t bT = aT + 20480;
#pragma unroll
            for (int kk = 0; kk < 2; kk++) {
                uint32_t af[4][4], bf[4][2];
                const int cb = kk * 32;   // bytes (16 bf16)
#pragma unroll
                for (int mi = 0; mi < 4; mi++)
                    ldsm_x4(af[mi], aT + (wm + mi * 16 + (lane & 15)) * 80
                                        + cb + ((lane >> 4) & 1) * 16);
#pragma unroll
                for (int ni = 0; ni < 4; ni++)
                    ldsm_x2(bf[ni], bT + (wn + ni * 8 + (lane & 7)) * 80
                                        + cb + ((lane >> 3) & 1) * 16);
#pragma unroll
                for (int mi = 0; mi < 4; mi++)
#pragma unroll
                    for (int ni = 0; ni < 4; ni++)
                        mma_bf16(acc[mi][ni], af[mi], bf[ni]);
            }
        } else {
            const float* Af = (const float*)(sm + s * 10240);
            const float* Bf = (const float*)(sm + 20480 + s * 10240);
#pragma unroll
            for (int kk = 0; kk < 2; kk++) {
                const int c0 = kk * 8;
                uint32_t af[4][4], bf[4][2];
#pragma unroll
                for (int mi = 0; mi < 4; mi++) {
                    int r0 = wm + mi * 16 + tr;
                    af[mi][0] = f2tf32(Af[r0 * 20 + c0 + tcq]);
                    af[mi][1] = f2tf32(Af[(r0 + 8) * 20 + c0 + tcq]);
                    af[mi][2] = f2tf32(Af[r0 * 20 + c0 + tcq + 4]);
                    af[mi][3] = f2tf32(Af[(r0 + 8) * 20 + c0 + tcq + 4]);
                }
#pragma unroll
                for (int ni = 0; ni < 4; ni++) {
                    int rn = wn + ni * 8 + tr;
                    bf[ni][0] = f2tf32(Bf[rn * 20 + c0 + tcq]);
                    bf[ni][1] = f2tf32(Bf[rn * 20 + c0 + tcq + 4]);
                }
#pragma unroll
                for (int mi = 0; mi < 4; mi++)
#pragma unroll
                    for (int ni = 0; ni < 4; ni++)
                        mma_tf32(acc[mi][ni], af[mi], bf[ni]);
            }
        }
        __syncthreads();
    }

    // ------------------------------ epilogue ------------------------------
    const int tc = (lane & 3) * 2;
    const long bzMN = (long)bz * M * N;
#pragma unroll
    for (int mi = 0; mi < 4; mi++) {
#pragma unroll
        for (int r2 = 0; r2 < 2; r2++) {
            const int m = bm + wm + mi * 16 + tr + r2 * 8;
            if (m >= M) continue;
#pragma unroll
            for (int ni = 0; ni < 4; ni++) {
                const int n = bn + wn + ni * 8 + tc;
                float v0 = acc[mi][ni][r2 * 2 + 0] * alpha;
                float v1 = acc[mi][ni][r2 * 2 + 1] * alpha;
                if (bias) { v0 += bias[n]; v1 += bias[n + 1]; }
                if (TOUT) {
                    const long i0 = bzMN + (long)n * M + m;
                    const long i1 = bzMN + (long)(n + 1) * M + m;
                    if (R) { v0 += rcoef * R[i0]; v1 += rcoef * R[i1]; }
                    if (Cf) { Cf[i0] = v0; Cf[i1] = v1; }
                    if (Cb) { Cb[i0] = __float2bfloat16(v0); Cb[i1] = __float2bfloat16(v1); }
                } else {
                    const long i0 = bzMN + (long)m * N + n;
                    if (R) {
                        float2 r2v = *(const float2*)(R + i0);
                        v0 += rcoef * r2v.x; v1 += rcoef * r2v.y;
                    }
                    if (Cf) *(float2*)(Cf + i0) = make_float2(v0, v1);
                    if (Cb) *(__nv_bfloat162*)(Cb + i0) = __floats2bfloat162_rn(v0, v1);
                }
            }
        }
    }
#undef LOAD_CHUNK
}

static void gemm(int dt, bool tout,
                 const void* A, long sA, const void* B, long sB,
                 float* Cf, __nv_bfloat16* Cb, const float* bias, const float* R,
                 float rcoef, float alpha, int M, int N, int K) {
    dim3 grid(N / 128, (M + 127) / 128, NB);
    if (dt == 0) {
        if (tout) gemm_mma<0, true ><<<grid, 256>>>(A, sA, B, sB, Cf, Cb, bias, R, rcoef, alpha, M, N, K);
        else      gemm_mma<0, false><<<grid, 256>>>(A, sA, B, sB, Cf, Cb, bias, R, rcoef, alpha, M, N, K);
    } else {
        if (tout) gemm_mma<1, true ><<<grid, 256>>>(A, sA, B, sB, Cf, Cb, bias, R, rcoef, alpha, M, N, K);
        else      gemm_mma<1, false><<<grid, 256>>>(A, sA, B, sB, Cf, Cb, bias, R, rcoef, alpha, M, N, K);
    }
}

// ===================== driver ================================================
extern "C" void kernel_launch(void* const* d_in, const int* in_sizes, int n_in,
                              void* d_out, int out_size) {
    const float* x      = (const float*)d_in[0];
    const float* ctx    = (const float*)d_in[1];
    const float* gn1_g  = (const float*)d_in[2];
    const float* gn1_b  = (const float*)d_in[3];
    const float* w_in   = (const float*)d_in[4];
    const float* b_in   = (const float*)d_in[5];
    const float* sa_wk  = (const float*)d_in[6];
    const float* sa_wq  = (const float*)d_in[7];
    const float* sa_wv  = (const float*)d_in[8];
    const float* sa_wp  = (const float*)d_in[9];
    const float* sa_gng = (const float*)d_in[10];
    const float* sa_gnb = (const float*)d_in[11];
    const float* ca_wq  = (const float*)d_in[12];
    const float* ca_wk  = (const float*)d_in[13];
    const float* ca_wv  = (const float*)d_in[14];
    const float* ca_wo  = (const float*)d_in[15];
    const float* ca_bo  = (const float*)d_in[16];
    const float* w_out  = (const float*)d_in[17];
    const float* b_out  = (const float*)d_in[18];
    float* out = (float*)d_out;

    float *xnf, *h0, *h1, *of, *kc, *vc;
    __nv_bfloat16 *wb, *hnb, *qb, *kb, *vtb, *h1b, *attn;
    cudaGetSymbolAddress((void**)&xnf, g_xnf);
    cudaGetSymbolAddress((void**)&h0,  g_h0);
    cudaGetSymbolAddress((void**)&h1,  g_h1);
    cudaGetSymbolAddress((void**)&of,  g_of);
    cudaGetSymbolAddress((void**)&kc,  g_kc);
    cudaGetSymbolAddress((void**)&vc,  g_vc);
    cudaGetSymbolAddress((void**)&wb,  g_wb);
    cudaGetSymbolAddress((void**)&hnb, g_hnb);
    cudaGetSymbolAddress((void**)&qb,  g_qb);
    cudaGetSymbolAddress((void**)&kb,  g_kb);
    cudaGetSymbolAddress((void**)&vtb, g_vtb);
    cudaGetSymbolAddress((void**)&h1b, g_h1b);
    cudaGetSymbolAddress((void**)&attn, g_attn);

    __nv_bfloat16* wb_saq = wb + 131072;
    __nv_bfloat16* wb_sak = wb + 393216;
    __nv_bfloat16* wb_sav = wb + 655360;
    __nv_bfloat16* wb_caq = wb + 1179648;
    __nv_bfloat16* wb_cak = wb + 1441792;
    __nv_bfloat16* wb_cav = wb + 1835008;
    __nv_bfloat16* ctx_b  = wb + 2621440;

    const float inv_sqrt_c = 0.044194173824159216f;   // 512^-0.5

    // 0. convert weights + ctx to bf16
    CvtSrc cs;
    cs.p[0] = w_in;  cs.p[1] = sa_wq; cs.p[2] = sa_wk; cs.p[3] = sa_wv;
    cs.p[4] = sa_wp; cs.p[5] = ca_wq; cs.p[6] = ca_wk; cs.p[7] = ca_wv;
    cs.p[8] = ca_wo; cs.p[9] = w_out; cs.p[10] = ctx;
    cvt_k<<<(int)((WB_TOTAL + 255) / 256), 256>>>(cs);

    // 1. GN1(x) -> xnf fp32 [b,n,c]
    gn1_stats_k<<<NB * 32, 256>>>(x);
    gn1_apply_k<<<NB * HW * CIN / 256, 256>>>(x, gn1_g, gn1_b);
    // 2. conv_in (tf32): h0 = xn @ w_in^T + b_in
    gemm(1, false, xnf, (long)HW * CIN, w_in, 0, h0, nullptr, b_in,
         nullptr, 0.f, 1.f, HW, INNER, CIN);
    // 3. GN2(h0) -> hnb bf16
    gn2_k<<<NB * 32, 256>>>(sa_gng, sa_gnb);
    // 4. q/k/v (bf16); v stored transposed
    gemm(0, false, hnb, (long)HW * INNER, wb_saq, 0, nullptr, qb, nullptr, nullptr, 0.f, 1.f, HW, INNER, INNER);
    gemm(0, false, hnb, (long)HW * INNER, wb_sak, 0, nullptr, kb, nullptr, nullptr, 0.f, 1.f, HW, INNER, INNER);
    gemm(0, true,  hnb, (long)HW * INNER, wb_sav, 0, nullptr, vtb, nullptr, nullptr, 0.f, 1.f, HW, INNER, INNER);
    // 5. sim = q @ k^T * c^-0.5 (bf16)
    gemm(0, false, qb, (long)HW * INNER, kb, (long)HW * INNER, nullptr, attn,
         nullptr, nullptr, 0.f, inv_sqrt_c, HW, HW, INNER);
    // 6. softmax
    softmax_k<<<NB * HW, 256>>>();
    // 7. o = attn @ v (bf16, fp32 out)
    gemm(0, false, attn, (long)HW * HW, vtb, (long)INNER * HW, of, nullptr,
         nullptr, nullptr, 0.f, 1.f, HW, INNER, HW);
    // 8. h1 = o @ wp^T + 2*h0 (tf32)
    gemm(1, false, of, (long)HW * INNER, sa_wp, 0, h1, h1b, nullptr,
         h0, 2.f, 1.f, HW, INNER, INNER);
    // 9. CA projections (bf16)
    gemm(0, false, h1b, (long)HW * INNER, wb_caq, 0, nullptr, qb, nullptr, nullptr, 0.f, 1.f, HW, INNER, INNER);
    gemm(0, false, ctx_b, (long)CTXN * CTXD, wb_cak, 0, kc, nullptr, nullptr, nullptr, 0.f, 1.f, CTXN, INNER, CTXD);
    gemm(0, false, ctx_b, (long)CTXN * CTXD, wb_cav, 0, vc, nullptr, nullptr, nullptr, 0.f, 1.f, CTXN, INNER, CTXD);
    // 10. fused cross-attention -> of (fp32)
    ca_attn_k<<<dim3(NB * 8, 4), 256>>>();
    // 11. h2 = o @ ca_wo^T + ca_bo + h1 (tf32) -> reuse h0
    gemm(1, false, of, (long)HW * INNER, ca_wo, 0, h0, nullptr, ca_bo,
         h1, 1.f, 1.f, HW, INNER, INNER);
    // 12. out = h2 @ w_out^T + b_out + x (tf32, TOUT -> NCHW)
    gemm(1, true, h0, (long)HW * INNER, w_out, 0, out, nullptr, b_out,
         x, 1.f, 1.f, HW, CIN, INNER);
}

// round 4
// speedup vs baseline: 4.5629x; 1.3592x over previous
#include <cuda_runtime.h>
#include <cuda_bf16.h>
#include <math.h>
#include <stdint.h>

#define NB    16
#define CIN   256
#define HW    1024
#define INNER 512
#define CTXN  77
#define CTXD  768
#define DH    64

// ===================== PTX helpers (sm_80-safe only) =========================
__device__ __forceinline__ uint32_t smem_to_u32(const void* p) {
    uint32_t a;
    asm("{ .reg .u64 t; cvta.to.shared.u64 t, %1; cvt.u32.u64 %0, t; }" : "=r"(a) : "l"(p));
    return a;
}
__device__ __forceinline__ void cp16(uint32_t dst, const void* src, bool valid) {
    int sz = valid ? 16 : 0;
    asm volatile("cp.async.cg.shared.global [%0], [%1], 16, %2;"
                 :: "r"(dst), "l"(src), "r"(sz) : "memory");
}
#define CP_COMMIT() asm volatile("cp.async.commit_group;" ::: "memory")
template <int N>
__device__ __forceinline__ void cp_wait() {
    asm volatile("cp.async.wait_group %0;" :: "n"(N) : "memory");
}
__device__ __forceinline__ void ldsm_x4(uint32_t* r, uint32_t addr) {
    asm volatile("ldmatrix.sync.aligned.m8n8.x4.shared.b16 {%0,%1,%2,%3}, [%4];"
        : "=r"(r[0]), "=r"(r[1]), "=r"(r[2]), "=r"(r[3]) : "r"(addr));
}
__device__ __forceinline__ void mma_bf16(float* d, const uint32_t* a,
                                         uint32_t b0, uint32_t b1) {
    asm volatile(
        "mma.sync.aligned.m16n8k16.row.col.f32.bf16.bf16.f32 "
        "{%0,%1,%2,%3}, {%4,%5,%6,%7}, {%8,%9}, {%0,%1,%2,%3};"
        : "+f"(d[0]), "+f"(d[1]), "+f"(d[2]), "+f"(d[3])
        : "r"(a[0]), "r"(a[1]), "r"(a[2]), "r"(a[3]), "r"(b0), "r"(b1));
}

// ===================== scratch (device globals) ==============================
#define WB_TOTAL 3567616L
__device__ __align__(16) __nv_bfloat16 g_wb[WB_TOTAL];
__device__ __align__(16) float g_h0 [NB * HW * INNER];
__device__ __align__(16) float g_h1 [NB * HW * INNER];
__device__ __align__(16) float g_kvc[NB * CTXN * 1024];
__device__ float g_stats[NB * 32 * 2];
__device__ __align__(16) __nv_bfloat16 g_xnb [NB * HW * CIN];
__device__ __align__(16) __nv_bfloat16 g_hnb [NB * HW * INNER];
__device__ __align__(16) __nv_bfloat16 g_qb  [NB * HW * INNER];
__device__ __align__(16) __nv_bfloat16 g_kb  [NB * HW * INNER];
__device__ __align__(16) __nv_bfloat16 g_vtb [NB * HW * INNER];
__device__ __align__(16) __nv_bfloat16 g_ob  [NB * HW * INNER];
__device__ __align__(16) __nv_bfloat16 g_h1b [NB * HW * INNER];
__device__ __align__(16) __nv_bfloat16 g_h2b [NB * HW * INNER];
__device__ __align__(16) __nv_bfloat16 g_attn[(long)NB * HW * HW];

// ===================== reductions ============================================
__device__ __forceinline__ float warpSum(float v) {
#pragma unroll
    for (int o = 16; o; o >>= 1) v += __shfl_xor_sync(0xffffffffu, v, o);
    return v;
}
__device__ float blockSum(float v) {
    __shared__ float sm[8];
    int t = threadIdx.x;
    v = warpSum(v);
    if ((t & 31) == 0) sm[t >> 5] = v;
    __syncthreads();
    if (t < 32) {
        float w = (t < 8) ? sm[t] : 0.f;
        w = warpSum(w);
        if (t == 0) sm[0] = w;
    }
    __syncthreads();
    float r = sm[0];
    __syncthreads();
    return r;
}
__device__ __forceinline__ float warpMax(float v) {
#pragma unroll
    for (int o = 16; o; o >>= 1) v = fmaxf(v, __shfl_xor_sync(0xffffffffu, v, o));
    return v;
}
__device__ float blockMax(float v) {
    __shared__ float sm[8];
    int t = threadIdx.x;
    v = warpMax(v);
    if ((t & 31) == 0) sm[t >> 5] = v;
    __syncthreads();
    if (t < 32) {
        float w = (t < 8) ? sm[t] : -3.0e38f;
        w = warpMax(w);
        if (t == 0) sm[0] = w;
    }
    __syncthreads();
    float r = sm[0];
    __syncthreads();
    return r;
}

// ===================== conversions ===========================================
struct CvtSrc { const float* p[11]; };
__global__ void cvt_k(CvtSrc a) {
    long i = (long)blockIdx.x * 256 + threadIdx.x;
    if (i >= WB_TOTAL) return;
    const long ends[11] = {131072, 393216, 655360, 917504, 1179648, 1441792,
                           1835008, 2228224, 2490368, 2621440, 3567616};
    int s = 0; long off = 0;
#pragma unroll
    for (int k = 0; k < 11; k++) {
        if (i >= ends[k]) { s = k + 1; off = ends[k]; }
    }
    g_wb[i] = __float2bfloat16(a.p[s][i - off]);
}

// ===================== GroupNorm 1 ===========================================
__global__ void gn1_stats_k(const float* __restrict__ x) {
    int bg = blockIdx.x;
    const float* p = x + (long)bg * 8192;
    float s = 0.f, ss = 0.f;
    for (int i = threadIdx.x; i < 2048; i += 256) {
        float4 v = ((const float4*)p)[i];
        s += v.x + v.y + v.z + v.w;
        ss += v.x * v.x + v.y * v.y + v.z * v.z + v.w * v.w;
    }
    s = blockSum(s); ss = blockSum(ss);
    if (threadIdx.x == 0) {
        float mean = s * (1.f / 8192.f);
        float var  = ss * (1.f / 8192.f) - mean * mean;
        g_stats[bg * 2]     = mean;
        g_stats[bg * 2 + 1] = rsqrtf(var + 1e-5f);
    }
}
__global__ void gn1_apply_k(const float* __restrict__ x,
                            const float* __restrict__ gam,
                            const float* __restrict__ bet) {
    int idx = blockIdx.x * 256 + threadIdx.x;   // [b,n,c] linear
    int c = idx & 255;
    int n = (idx >> 8) & 1023;
    int b = idx >> 18;
    float v = x[((long)(b * 256 + c)) * 1024 + n];
    int sg = (b << 5) | (c >> 3);
    float mean = g_stats[sg * 2], rstd = g_stats[sg * 2 + 1];
    g_xnb[idx] = __float2bfloat16((v - mean) * rstd * gam[c] + bet[c]);
}

// ===================== GroupNorm 2 (h0 fp32 -> hnb bf16) =====================
__global__ void gn2_k(const float* __restrict__ gg, const float* __restrict__ gb) {
    int b = blockIdx.x >> 5, g = blockIdx.x & 31;   // 16 ch per group
    const float4* p = (const float4*)(g_h0 + (long)b * HW * INNER + g * 16);
    float s = 0.f, ss = 0.f;
    for (int i = threadIdx.x; i < HW * 4; i += 256) {
        int n = i >> 2, j = i & 3;
        float4 v = p[n * 128 + j];
        s += v.x + v.y + v.z + v.w;
        ss += v.x * v.x + v.y * v.y + v.z * v.z + v.w * v.w;
    }
    s = blockSum(s); ss = blockSum(ss);
    float mean = s * (1.f / 16384.f);
    float rstd = rsqrtf(ss * (1.f / 16384.f) - mean * mean + 1e-5f);
    __nv_bfloat16* q = g_hnb + (long)b * HW * INNER + g * 16;
    const float* pf = g_h0 + (long)b * HW * INNER + g * 16;
    for (int i = threadIdx.x; i < HW * 4; i += 256) {
        int n = i >> 2, j = i & 3;
        int c = g * 16 + j * 4;
        float4 v = p[n * 128 + j];
        __nv_bfloat162 o0 = __floats2bfloat162_rn(
            (v.x - mean) * rstd * gg[c] + gb[c],
            (v.y - mean) * rstd * gg[c + 1] + gb[c + 1]);
        __nv_bfloat162 o1 = __floats2bfloat162_rn(
            (v.z - mean) * rstd * gg[c + 2] + gb[c + 2],
            (v.w - mean) * rstd * gg[c + 3] + gb[c + 3]);
        *(uint2*)(q + n * INNER + j * 4) = make_uint2(
            *(uint32_t*)&o0, *(uint32_t*)&o1);
    }
    (void)pf;
}

// ===================== softmax over 1024 (bf16 in/out) =======================
__global__ void softmax_k() {
    __nv_bfloat162* row = (__nv_bfloat162*)(g_attn + (long)blockIdx.x * HW);
    int t = threadIdx.x;
    __nv_bfloat162 a = row[t * 2], b = row[t * 2 + 1];
    float2 fa = __bfloat1622float2(a), fb = __bfloat1622float2(b);
    float m = blockMax(fmaxf(fmaxf(fa.x, fa.y), fmaxf(fb.x, fb.y)));
    fa.x = __expf(fa.x - m); fa.y = __expf(fa.y - m);
    fb.x = __expf(fb.x - m); fb.y = __expf(fb.y - m);
    float inv = 1.f / blockSum(fa.x + fa.y + fb.x + fb.y);
    fa.x *= inv; fa.y *= inv; fb.x *= inv; fb.y *= inv;
    row[t * 2]     = __floats2bfloat162_rn(fa.x, fa.y);
    row[t * 2 + 1] = __floats2bfloat162_rn(fb.x, fb.y);
}

// ===================== fused cross-attention =================================
// kvc: [b][77][1024] fp32 (k | v per row). q bf16. out bf16.
__global__ void __launch_bounds__(256) ca_attn_k() {
    __shared__ float Ks[CTXN][DH];
    __shared__ float Vs[CTXN][DH];
    int b = blockIdx.x >> 3, h = blockIdx.x & 7;
    const float* kp = g_kvc + (long)b * CTXN * 1024 + h * DH;
    for (int i = threadIdx.x; i < CTXN * DH; i += 256) {
        int j = i >> 6, d = i & 63;
        Ks[j][d] = kp[j * 1024 + d];
        Vs[j][d] = kp[j * 1024 + 512 + d];
    }
    __syncthreads();
    const float scale = 0.125f;
    int i = blockIdx.y * 256 + threadIdx.x;
    const __nv_bfloat16* qp = g_qb + ((long)(b * HW + i)) * INNER + h * DH;
    float qv[DH];
#pragma unroll
    for (int d = 0; d < DH; d += 8) {
        uint4 u = *(const uint4*)(qp + d);
        const __nv_bfloat162* h2 = (const __nv_bfloat162*)&u;
#pragma unroll
        for (int e = 0; e < 4; e++) {
            float2 f = __bfloat1622float2(h2[e]);
            qv[d + 2 * e] = f.x; qv[d + 2 * e + 1] = f.y;
        }
    }
    float l = 0.f, acc[DH];
#pragma unroll
    for (int d = 0; d < DH; d++) acc[d] = 0.f;
    for (int j = 0; j < CTXN; j++) {
        float s = 0.f;
#pragma unroll
        for (int d = 0; d < DH; d++) s += qv[d] * Ks[j][d];
        float e = __expf(s * scale);
        l += e;
#pragma unroll
        for (int d = 0; d < DH; d++) acc[d] += e * Vs[j][d];
    }
    float inv = 1.f / l;
    __nv_bfloat16* op = g_ob + ((long)(b * HW + i)) * INNER + h * DH;
#pragma unroll
    for (int d = 0; d < DH; d += 8) {
        __nv_bfloat162 pk[4];
#pragma unroll
        for (int e = 0; e < 4; e++)
            pk[e] = __floats2bfloat162_rn(acc[d + 2 * e] * inv, acc[d + 2 * e + 1] * inv);
        *(uint4*)(op + d) = *(uint4*)pk;
    }
}

// ===================== bf16 mma.sync GEMM, 3-stage cp.async ==================
// C[bz] = alpha * A[bz] @ B[bz]^T (+ bias[n]) (+ rcoef * R)
// A: bf16 [M,K] row-major; B: bf16 [N,K] row-major.
// 128x128 CTA tile, 8 warps (2x4), 64x32 warp tiles, BK=64, XOR-swizzled smem.
// TOUT: store (and read R) at [bz*M*N + n*M + m].
#define STAGE_B 32768
#define GSMEM   (3 * STAGE_B)

template <bool TOUT>
__global__ void __launch_bounds__(256) gemm_mma(
    const __nv_bfloat16* __restrict__ A_, long sA,
    const __nv_bfloat16* __restrict__ B_, long sB,
    float* __restrict__ Cf, __nv_bfloat16* __restrict__ Cb,
    const float* __restrict__ bias, const float* __restrict__ R,
    float rcoef, float alpha, int M, int N, int K) {
    extern __shared__ __align__(128) char sm[];
    const uint32_t sb = smem_to_u32(sm);
    const int tid  = threadIdx.x;
    const int lane = tid & 31;
    const int wid  = tid >> 5;
    const int bz = blockIdx.z;
    const int bm = blockIdx.y * 128;
    const int bn = blockIdx.x * 128;
    const int wm = (wid >> 2) * 64;
    const int wn = (wid & 3) * 32;
    const __nv_bfloat16* Ab = A_ + (long)bz * sA;
    const __nv_bfloat16* Bb = B_ + (long)bz * sB;

    float acc[4][4][4];
#pragma unroll
    for (int i = 0; i < 4; i++)
#pragma unroll
        for (int j = 0; j < 4; j++)
#pragma unroll
            for (int e = 0; e < 4; e++) acc[i][j][e] = 0.f;

    // loader mapping: row = tid>>1 (0..127), units (tid&1)*4 + 0..3
    const int lrow = tid >> 1;
    const int lu0  = (tid & 1) * 4;
    const bool aValid = (bm + lrow) < M;
    const long aRow = aValid ? (long)(bm + lrow) * K : 0;
    const long bRow = (long)(bn + lrow) * K;
    const uint32_t sAo = lrow * 128;
    const int nIter = K >> 6;

#define LOADC(i, s) do {                                                        \
    uint32_t dA = sb + (s) * STAGE_B + sAo;                                     \
    uint32_t dB = dA + 16384;                                                   \
    const __nv_bfloat16* gA = Ab + aRow + ((long)(i) << 6);                     \
    const __nv_bfloat16* gB = Bb + bRow + ((long)(i) << 6);                     \
    _Pragma("unroll")                                                           \
    for (int j = 0; j < 4; j++) {                                               \
        int u = lu0 + j;                                                        \
        uint32_t so = (uint32_t)((u ^ (lrow & 7)) << 4);                        \
        cp16(dA + so, gA + u * 8, aValid);                                      \
        cp16(dB + so, gB + u * 8, true);                                        \
    }                                                                           \
} while (0)

    LOADC(0, 0); CP_COMMIT();
    if (1 < nIter) { LOADC(1, 1); }
    CP_COMMIT();

    const int arow = lane & 15;          // ldsm row within 16
    const int ahalf = (lane >> 4) & 1;   // 16B half selector

    for (int it = 0; it < nIter; it++) {
        const int s = it % 3;
        if (it + 1 < nIter) cp_wait<1>(); else cp_wait<0>();
        __syncthreads();
        if (it + 2 < nIter) { LOADC(it + 2, (it + 2) % 3); CP_COMMIT(); }

        const uint32_t aT = sb + s * STAGE_B;
        const uint32_t bT = aT + 16384;
#pragma unroll
        for (int kk = 0; kk < 4; kk++) {
            const int u = kk * 2 + ahalf;
            uint32_t af[4][4], bf[2][4];
#pragma unroll
            for (int mi = 0; mi < 4; mi++) {
                int r = wm + mi * 16 + arow;
                ldsm_x4(af[mi], aT + r * 128 + ((u ^ (r & 7)) << 4));
            }
#pragma unroll
            for (int p = 0; p < 2; p++) {
                int r = wn + p * 16 + arow;
                ldsm_x4(bf[p], bT + r * 128 + ((u ^ (r & 7)) << 4));
            }
#pragma unroll
            for (int mi = 0; mi < 4; mi++)
#pragma unroll
                for (int p = 0; p < 2; p++) {
                    mma_bf16(acc[mi][2 * p],     af[mi], bf[p][0], bf[p][2]);
                    mma_bf16(acc[mi][2 * p + 1], af[mi], bf[p][1], bf[p][3]);
                }
        }
        __syncthreads();
    }

    // ------------------------------ epilogue ------------------------------
    const int tr = lane >> 2;
    const int tc = (lane & 3) * 2;
    const long bzMN = (long)bz * M * N;
#pragma unroll
    for (int mi = 0; mi < 4; mi++) {
#pragma unroll
        for (int r2 = 0; r2 < 2; r2++) {
            const int m = bm + wm + mi * 16 + tr + r2 * 8;
            if (m >= M) continue;
#pragma unroll
            for (int ni = 0; ni < 4; ni++) {
                const int n = bn + wn + ni * 8 + tc;
                float v0 = acc[mi][ni][r2 * 2 + 0] * alpha;
                float v1 = acc[mi][ni][r2 * 2 + 1] * alpha;
                if (bias) { v0 += bias[n]; v1 += bias[n + 1]; }
                if (TOUT) {
                    const long i0 = bzMN + (long)n * M + m;
                    const long i1 = bzMN + (long)(n + 1) * M + m;
                    if (R) { v0 += rcoef * R[i0]; v1 += rcoef * R[i1]; }
                    if (Cf) { Cf[i0] = v0; Cf[i1] = v1; }
                    if (Cb) { Cb[i0] = __float2bfloat16(v0); Cb[i1] = __float2bfloat16(v1); }
                } else {
                    const long i0 = bzMN + (long)m * N + n;
                    if (R) {
                        float2 rv = *(const float2*)(R + i0);
                        v0 += rcoef * rv.x; v1 += rcoef * rv.y;
                    }
                    if (Cf) *(float2*)(Cf + i0) = make_float2(v0, v1);
                    if (Cb) *(__nv_bfloat162*)(Cb + i0) = __floats2bfloat162_rn(v0, v1);
                }
            }
        }
    }
#undef LOADC
}

static void gemm(bool tout,
                 const __nv_bfloat16* A, long sA, const __nv_bfloat16* B, long sB,
                 float* Cf, __nv_bfloat16* Cb, const float* bias, const float* R,
                 float rcoef, float alpha, int M, int N, int K) {
    dim3 grid(N / 128, (M + 127) / 128, NB);
    if (tout) gemm_mma<true ><<<grid, 256, GSMEM>>>(A, sA, B, sB, Cf, Cb, bias, R, rcoef, alpha, M, N, K);
    else      gemm_mma<false><<<grid, 256, GSMEM>>>(A, sA, B, sB, Cf, Cb, bias, R, rcoef, alpha, M, N, K);
}

// ===================== driver ================================================
extern "C" void kernel_launch(void* const* d_in, const int* in_sizes, int n_in,
                              void* d_out, int out_size) {
    const float* x      = (const float*)d_in[0];
    const float* ctx    = (const float*)d_in[1];
    const float* gn1_g  = (const float*)d_in[2];
    const float* gn1_b  = (const float*)d_in[3];
    const float* w_in   = (const float*)d_in[4];
    const float* b_in   = (const float*)d_in[5];
    const float* sa_wk  = (const float*)d_in[6];
    const float* sa_wq  = (const float*)d_in[7];
    const float* sa_wv  = (const float*)d_in[8];
    const float* sa_wp  = (const float*)d_in[9];
    const float* sa_gng = (const float*)d_in[10];
    const float* sa_gnb = (const float*)d_in[11];
    const float* ca_wq  = (const float*)d_in[12];
    const float* ca_wk  = (const float*)d_in[13];
    const float* ca_wv  = (const float*)d_in[14];
    const float* ca_wo  = (const float*)d_in[15];
    const float* ca_bo  = (const float*)d_in[16];
    const float* w_out  = (const float*)d_in[17];
    const float* b_out  = (const float*)d_in[18];
    float* out = (float*)d_out;

    static int s_attr = 0;
    if (!s_attr) {
        cudaFuncSetAttribute(gemm_mma<true>,  cudaFuncAttributeMaxDynamicSharedMemorySize, GSMEM);
        cudaFuncSetAttribute(gemm_mma<false>, cudaFuncAttributeMaxDynamicSharedMemorySize, GSMEM);
        s_attr = 1;
    }

    float *h0, *h1, *kvc;
    __nv_bfloat16 *wb, *xnb, *hnb, *qb, *kb, *vtb, *ob, *h1b, *h2b, *attn;
    cudaGetSymbolAddress((void**)&h0,  g_h0);
    cudaGetSymbolAddress((void**)&h1,  g_h1);
    cudaGetSymbolAddress((void**)&kvc, g_kvc);
    cudaGetSymbolAddress((void**)&wb,  g_wb);
    cudaGetSymbolAddress((void**)&xnb, g_xnb);
    cudaGetSymbolAddress((void**)&hnb, g_hnb);
    cudaGetSymbolAddress((void**)&qb,  g_qb);
    cudaGetSymbolAddress((void**)&kb,  g_kb);
    cudaGetSymbolAddress((void**)&vtb, g_vtb);
    cudaGetSymbolAddress((void**)&ob,  g_ob);
    cudaGetSymbolAddress((void**)&h1b, g_h1b);
    cudaGetSymbolAddress((void**)&h2b, g_h2b);
    cudaGetSymbolAddress((void**)&attn, g_attn);

    __nv_bfloat16* wb_in  = wb;
    __nv_bfloat16* wb_saq = wb + 131072;
    __nv_bfloat16* wb_sak = wb + 393216;
    __nv_bfloat16* wb_sav = wb + 655360;
    __nv_bfloat16* wb_sap = wb + 917504;
    __nv_bfloat16* wb_caq = wb + 1179648;
    __nv_bfloat16* wb_cakv= wb + 1441792;   // k then v, contiguous [1024, 768]
    __nv_bfloat16* wb_cao = wb + 2228224;
    __nv_bfloat16* wb_out = wb + 2490368;
    __nv_bfloat16* ctx_b  = wb + 2621440;

    const float inv_sqrt_c = 0.044194173824159216f;   // 512^-0.5

    // 0. convert weights + ctx to bf16
    CvtSrc cs;
    cs.p[0] = w_in;  cs.p[1] = sa_wq; cs.p[2] = sa_wk; cs.p[3] = sa_wv;
    cs.p[4] = sa_wp; cs.p[5] = ca_wq; cs.p[6] = ca_wk; cs.p[7] = ca_wv;
    cs.p[8] = ca_wo; cs.p[9] = w_out; cs.p[10] = ctx;
    cvt_k<<<(int)((WB_TOTAL + 255) / 256), 256>>>(cs);

    // 1. GN1(x) -> xnb bf16 [b,n,c]
    gn1_stats_k<<<NB * 32, 256>>>(x);
    gn1_apply_k<<<NB * HW * CIN / 256, 256>>>(x, gn1_g, gn1_b);
    // 2. conv_in: h0 = xn @ w_in^T + b_in (fp32)
    gemm(false, xnb, (long)HW * CIN, wb_in, 0, h0, nullptr, b_in,
         nullptr, 0.f, 1.f, HW, INNER, CIN);
    // 3. GN2(h0) -> hnb bf16
    gn2_k<<<NB * 32, 256>>>(sa_gng, sa_gnb);
    // 4. q/k/v; v stored transposed
    gemm(false, hnb, (long)HW * INNER, wb_saq, 0, nullptr, qb, nullptr, nullptr, 0.f, 1.f, HW, INNER, INNER);
    gemm(false, hnb, (long)HW * INNER, wb_sak, 0, nullptr, kb, nullptr, nullptr, 0.f, 1.f, HW, INNER, INNER);
    gemm(true,  hnb, (long)HW * INNER, wb_sav, 0, nullptr, vtb, nullptr, nullptr, 0.f, 1.f, HW, INNER, INNER);
    // 5. sim = q @ k^T * c^-0.5 -> attn bf16
    gemm(false, qb, (long)HW * INNER, kb, (long)HW * INNER, nullptr, attn,
         nullptr, nullptr, 0.f, inv_sqrt_c, HW, HW, INNER);
    // 6. softmax
    softmax_k<<<NB * HW, 256>>>();
    // 7. o = attn @ v -> ob bf16
    gemm(false, attn, (long)HW * HW, vtb, (long)INNER * HW, nullptr, ob,
         nullptr, nullptr, 0.f, 1.f, HW, INNER, HW);
    // 8. h1 = o @ wp^T + 2*h0 (fp32 + bf16 copies)
    gemm(false, ob, (long)HW * INNER, wb_sap, 0, h1, h1b, nullptr,
         h0, 2.f, 1.f, HW, INNER, INNER);
    // 9. CA projections: q (bf16) and fused k|v (fp32)
    gemm(false, h1b, (long)HW * INNER, wb_caq, 0, nullptr, qb, nullptr, nullptr, 0.f, 1.f, HW, INNER, INNER);
    gemm(false, ctx_b, (long)CTXN * CTXD, wb_cakv, 0, kvc, nullptr, nullptr, nullptr, 0.f, 1.f, CTXN, 1024, CTXD);
    // 10. fused cross-attention -> ob bf16
    ca_attn_k<<<dim3(NB * 8, 4), 256>>>();
    // 11. h2 = o @ ca_wo^T + ca_bo + h1 -> h2b bf16
    gemm(false, ob, (long)HW * INNER, wb_cao, 0, nullptr, h2b, ca_bo,
         h1, 1.f, 1.f, HW, INNER, INNER);
    // 12. out = h2 @ w_out^T + b_out + x (TOUT -> NCHW fp32)
    gemm(true, h2b, (long)HW * INNER, wb_out, 0, out, nullptr, b_out,
         x, 1.f, 1.f, HW, CIN, INNER);
}